// round 8
// baseline (speedup 1.0000x reference)
#include <cuda_runtime.h>
#include <cuda_bf16.h>

// ---------------- scratch (static device memory; no allocation) ----------------
__device__ float         g_P [65536ull * 512];   // q|k|v|g projections (row-major)
__device__ float         g_GA[65536ull * 128];   // gate * attn_out (row-major)
__device__ __nv_bfloat16 g_znh[8388608];          // layernormed z hi [token][128]
__device__ __nv_bfloat16 g_znl[8388608];          // layernormed z lo
__device__ __nv_bfloat16 g_Wh[65536], g_Wl[65536];   // packed q|k|v|g weights [512][128]
__device__ __nv_bfloat16 g_Oh[16384], g_Ol[16384];   // o_w [128][128]
__device__ float         g_Bcat[512];                 // packed q|k|v|g biases

typedef unsigned long long u64;

// ---------------- f32x2 packed-FMA helpers ----------------
__device__ __forceinline__ u64 frep2(float x) {
    u64 r; asm("mov.b64 %0, {%1, %1};" : "=l"(r) : "f"(x)); return r;
}
__device__ __forceinline__ void ffma2(u64& d, u64 a, u64 b) {
    asm("fma.rn.f32x2 %0, %1, %2, %0;" : "+l"(d) : "l"(a), "l"(b));
}
__device__ __forceinline__ float2 funpk(u64 d) {
    float2 f; asm("mov.b64 {%0, %1}, %2;" : "=f"(f.x), "=f"(f.y) : "l"(d)); return f;
}

// ---------------- tensor-core helpers ----------------
__device__ __forceinline__ unsigned smem_u32p(const void* p) {
    return (unsigned)__cvta_generic_to_shared(p);
}
__device__ __forceinline__ void ldmx4(unsigned* r, unsigned addr) {
    asm volatile("ldmatrix.sync.aligned.m8n8.x4.shared.b16 {%0,%1,%2,%3}, [%4];"
        : "=r"(r[0]), "=r"(r[1]), "=r"(r[2]), "=r"(r[3]) : "r"(addr));
}
__device__ __forceinline__ void ldmx2(unsigned* r, unsigned addr) {
    asm volatile("ldmatrix.sync.aligned.m8n8.x2.shared.b16 {%0,%1}, [%2];"
        : "=r"(r[0]), "=r"(r[1]) : "r"(addr));
}
__device__ __forceinline__ void mma16816(float* c, const unsigned* a, const unsigned* b) {
    asm volatile("mma.sync.aligned.m16n8k16.row.col.f32.bf16.bf16.f32 "
        "{%0,%1,%2,%3}, {%4,%5,%6,%7}, {%8,%9}, {%0,%1,%2,%3};"
        : "+f"(c[0]), "+f"(c[1]), "+f"(c[2]), "+f"(c[3])
        : "r"(a[0]), "r"(a[1]), "r"(a[2]), "r"(a[3]), "r"(b[0]), "r"(b[1]));
}
__device__ __forceinline__ void bf16split(float x, __nv_bfloat16& h, __nv_bfloat16& l) {
    h = __float2bfloat16_rn(x);
    l = __float2bfloat16_rn(x - __bfloat162float(h));
}

// ---------------- K0: pack + split weights ----------------
__global__ void pack_kernel(const float* __restrict__ qw, const float* __restrict__ kw,
                            const float* __restrict__ vw, const float* __restrict__ gw,
                            const float* __restrict__ qb, const float* __restrict__ kb,
                            const float* __restrict__ vb, const float* __restrict__ gb,
                            const float* __restrict__ ow) {
    int idx = blockIdx.x * 256 + threadIdx.x;   // 0 .. 81919
    if (idx < 65536) {
        int row = idx >> 7, col = idx & 127;
        const float* w = (row < 128) ? qw : (row < 256) ? kw : (row < 384) ? vw : gw;
        float x = w[(row & 127) * 128 + col];
        __nv_bfloat16 h, l; bf16split(x, h, l);
        g_Wh[idx] = h; g_Wl[idx] = l;
        if (idx < 512) {
            const float* b = (idx < 128) ? qb : (idx < 256) ? kb : (idx < 384) ? vb : gb;
            g_Bcat[idx] = b[idx & 127];
        }
    } else if (idx < 81920) {
        int i = idx - 65536;
        __nv_bfloat16 h, l; bf16split(ow[i], h, l);
        g_Oh[i] = h; g_Ol[i] = l;
    }
}

// ---------------- K1: LayerNorm -> bf16 hi/lo ----------------
__global__ void ln_kernel(const float* __restrict__ z,
                          const float* __restrict__ lw,
                          const float* __restrict__ lb) {
    int warp = threadIdx.x >> 5, lane = threadIdx.x & 31;
    int t = blockIdx.x * 8 + warp;
    const float4* zp = (const float4*)(z + (size_t)t * 128);
    float4 v = zp[lane];
    float s = v.x + v.y + v.z + v.w;
    float q = v.x * v.x + v.y * v.y + v.z * v.z + v.w * v.w;
    #pragma unroll
    for (int o = 16; o; o >>= 1) {
        s += __shfl_xor_sync(0xFFFFFFFFu, s, o);
        q += __shfl_xor_sync(0xFFFFFFFFu, q, o);
    }
    float mu  = s * (1.0f / 128.0f);
    float var = q * (1.0f / 128.0f) - mu * mu;
    float rs  = rsqrtf(var + 1e-5f);
    float4 w4 = ((const float4*)lw)[lane];
    float4 b4 = ((const float4*)lb)[lane];
    float o4[4];
    o4[0] = (v.x - mu) * rs * w4.x + b4.x;
    o4[1] = (v.y - mu) * rs * w4.y + b4.y;
    o4[2] = (v.z - mu) * rs * w4.z + b4.z;
    o4[3] = (v.w - mu) * rs * w4.w + b4.w;
    __nv_bfloat16 h[4], l[4];
    #pragma unroll
    for (int i = 0; i < 4; i++) bf16split(o4[i], h[i], l[i]);
    size_t base = (size_t)t * 128 + lane * 4;
    *(__nv_bfloat162*)(g_znh + base)     = __nv_bfloat162(h[0], h[1]);
    *(__nv_bfloat162*)(g_znh + base + 2) = __nv_bfloat162(h[2], h[3]);
    *(__nv_bfloat162*)(g_znl + base)     = __nv_bfloat162(l[0], l[1]);
    *(__nv_bfloat162*)(g_znl + base + 2) = __nv_bfloat162(l[2], l[3]);
}

// ---------------- K2/K4: bf16-split tensor-core GEMM (unchanged) ----------------
template<int MODE>
__global__ void __launch_bounds__(256, 2) mma_gemm(const float* __restrict__ obias,
                                                   const int*   __restrict__ mask,
                                                   float* __restrict__ Cout) {
    extern __shared__ __nv_bfloat16 smem[];
    __nv_bfloat16* sAh = smem;             // 64*136
    __nv_bfloat16* sAl = smem + 8704;
    __nv_bfloat16* sBh = smem + 17408;     // 128*136
    __nv_bfloat16* sBl = smem + 34816;
    int tid = threadIdx.x;
    int bm0 = blockIdx.x * 64;
    int bn0 = (MODE == 1) ? blockIdx.y * 128 : 0;

    if (MODE == 1) {
        const uint4* srcH = (const uint4*)(g_znh + (size_t)bm0 * 128);
        const uint4* srcL = (const uint4*)(g_znl + (size_t)bm0 * 128);
        uint4* dAh = (uint4*)sAh; uint4* dAl = (uint4*)sAl;
        #pragma unroll
        for (int it = 0; it < 4; it++) {
            int idx = it * 256 + tid;
            int row = idx >> 4, ch = idx & 15;
            dAh[row * 17 + ch] = srcH[idx];
            dAl[row * 17 + ch] = srcL[idx];
        }
    } else {
        const float4* srcA = (const float4*)(g_GA + (size_t)bm0 * 128);
        #pragma unroll
        for (int it = 0; it < 8; it++) {
            int idx = it * 256 + tid;
            int row = idx >> 5, c4 = idx & 31;
            float4 v = srcA[idx];
            int col = c4 * 4;
            __nv_bfloat16 h, l;
            bf16split(v.x, h, l); sAh[row * 136 + col]     = h; sAl[row * 136 + col]     = l;
            bf16split(v.y, h, l); sAh[row * 136 + col + 1] = h; sAl[row * 136 + col + 1] = l;
            bf16split(v.z, h, l); sAh[row * 136 + col + 2] = h; sAl[row * 136 + col + 2] = l;
            bf16split(v.w, h, l); sAh[row * 136 + col + 3] = h; sAl[row * 136 + col + 3] = l;
        }
    }
    {
        const __nv_bfloat16* BH = (MODE == 1) ? g_Wh : g_Oh;
        const __nv_bfloat16* BL = (MODE == 1) ? g_Wl : g_Ol;
        const uint4* srcH = (const uint4*)(BH + (size_t)bn0 * 128);
        const uint4* srcL = (const uint4*)(BL + (size_t)bn0 * 128);
        uint4* dBh = (uint4*)sBh; uint4* dBl = (uint4*)sBl;
        #pragma unroll
        for (int it = 0; it < 8; it++) {
            int idx = it * 256 + tid;
            int row = idx >> 4, ch = idx & 15;
            dBh[row * 17 + ch] = srcH[idx];
            dBl[row * 17 + ch] = srcL[idx];
        }
    }
    __syncthreads();

    int wid = tid >> 5, lane = tid & 31;
    int warp_m = (wid & 1) * 32, warp_n = (wid >> 1) * 32;
    unsigned baseAh = smem_u32p(sAh), baseAl = smem_u32p(sAl);
    unsigned baseBh = smem_u32p(sBh), baseBl = smem_u32p(sBl);
    int arow = warp_m + (lane & 15);
    int kofa = (lane >> 4) * 8;
    int brow = warp_n + (lane & 7);
    int kofb = ((lane >> 3) & 1) * 8;

    float acc[2][4][4];
    #pragma unroll
    for (int mi = 0; mi < 2; mi++)
        #pragma unroll
        for (int ni = 0; ni < 4; ni++)
            #pragma unroll
            for (int c = 0; c < 4; c++) acc[mi][ni][c] = 0.0f;

    #pragma unroll
    for (int ks = 0; ks < 8; ks++) {
        unsigned ah[2][4], al[2][4], bh[4][2], bl[4][2];
        #pragma unroll
        for (int mi = 0; mi < 2; mi++) {
            unsigned ao = (unsigned)((arow + mi * 16) * 272 + (ks * 16 + kofa) * 2);
            ldmx4(ah[mi], baseAh + ao);
            ldmx4(al[mi], baseAl + ao);
        }
        #pragma unroll
        for (int ni = 0; ni < 4; ni++) {
            unsigned bo = (unsigned)((brow + ni * 8) * 272 + (ks * 16 + kofb) * 2);
            ldmx2(bh[ni], baseBh + bo);
            ldmx2(bl[ni], baseBl + bo);
        }
        #pragma unroll
        for (int mi = 0; mi < 2; mi++)
            #pragma unroll
            for (int ni = 0; ni < 4; ni++) {
                mma16816(acc[mi][ni], ah[mi], bh[ni]);
                mma16816(acc[mi][ni], ah[mi], bl[ni]);
                mma16816(acc[mi][ni], al[mi], bh[ni]);
            }
    }

    #pragma unroll
    for (int mi = 0; mi < 2; mi++)
        #pragma unroll
        for (int ni = 0; ni < 4; ni++) {
            int row = bm0 + warp_m + mi * 16 + (lane >> 2);
            int col = bn0 + warp_n + ni * 8 + (lane & 3) * 2;
            if (MODE == 1) {
                float b0 = g_Bcat[col], b1 = g_Bcat[col + 1];
                *(float2*)&g_P[(size_t)row * 512 + col] =
                    make_float2(acc[mi][ni][0] + b0, acc[mi][ni][1] + b1);
                *(float2*)&g_P[(size_t)(row + 8) * 512 + col] =
                    make_float2(acc[mi][ni][2] + b0, acc[mi][ni][3] + b1);
            } else {
                float b0 = obias[col], b1 = obias[col + 1];
                float m0 = (float)mask[row], m1 = (float)mask[row + 8];
                *(float2*)&Cout[(size_t)row * 128 + col] =
                    make_float2((acc[mi][ni][0] + b0) * m0, (acc[mi][ni][1] + b1) * m0);
                *(float2*)&Cout[(size_t)(row + 8) * 128 + col] =
                    make_float2((acc[mi][ni][2] + b0) * m1, (acc[mi][ni][3] + b1) * m1);
            }
        }
}

// ---------------- K3: attn — token-chunked, low-reg, 3 CTAs/SM ----------------
// grid (256 rows, 4 heads), 256 threads, dyn smem 56448 B.
// floats: R1 @0 [8448]  : kf[128][66] | kvp[2][4][1024]+ksp[256] | q[256][33] | g/out[256][33]
//         R2 @8448 [4352]: k-stage[128][33] | vm[128][34] | kv[2048]+ks[64]
//         s_w @12800 [1056], s_mask @13856 [256]
__global__ void __launch_bounds__(256, 3) attn_kernel(const int*   __restrict__ pm,
                                                      const float* __restrict__ qfw,
                                                      const float* __restrict__ qfb,
                                                      const float* __restrict__ kfw,
                                                      const float* __restrict__ kfb) {
    extern __shared__ float sm[];
    float* R1     = sm;             // 8448
    float* R2     = sm + 8448;      // 4352
    float* s_w    = sm + 12800;     // 1056
    float* s_mask = sm + 13856;     // 256

    int tid = threadIdx.x;
    int r = blockIdx.x, h = blockIdx.y;
    int t0 = r * 256;
    int lane = tid & 31, w = tid >> 5;

    for (int i = tid; i < 1024; i += 256) s_w[i] = kfw[i];
    if (tid < 32) s_w[1024 + tid] = kfb[tid];
    s_mask[tid] = (float)pm[t0 + tid];

    // step-B decomposition: warp = (fhalf, tgroup); lane = (fy, dx); 4f x 8d per lane
    int fhalf = w & 1, tg = w >> 1;
    int fy = lane >> 2, dx = lane & 3;
    int fbase = fhalf * 32 + fy * 4;
    u64 acc2[4][4];
    float ks[4];
    #pragma unroll
    for (int j = 0; j < 4; j++) {
        ks[j] = 0.0f;
        #pragma unroll
        for (int q = 0; q < 4; q++) acc2[j][q] = 0ull;
    }
    __syncthreads();

    #pragma unroll 1
    for (int c = 0; c < 2; c++) {
        // ---- stage k chunk (coalesced) -> R2 [128][33] ----
        {
            const float* Pk0 = g_P + (size_t)(t0 + c * 128) * 512 + 128 + h * 32;
            #pragma unroll
            for (int it = 0; it < 4; it++) {
                int idx = it * 256 + tid;          // 0..1023
                int token = idx >> 3, c4 = idx & 7;
                float4 v = *(const float4*)(Pk0 + (size_t)token * 512 + c4 * 4);
                float* d = R2 + token * 33 + c4 * 4;
                d[0] = v.x; d[1] = v.y; d[2] = v.z; d[3] = v.w;
            }
        }
        __syncthreads();
        // ---- features: thread -> (token = tid&127, half = tid>>7), 2 jg groups ----
        {
            int tk = tid & 127, hh = tid >> 7;
            float mk = s_mask[c * 128 + tk];
            const float* kst = R2 + tk * 33;
            #pragma unroll
            for (int g2 = 0; g2 < 2; g2++) {
                int jg = hh * 2 + g2;
                float a8[8];
                #pragma unroll
                for (int jj = 0; jj < 8; jj++) a8[jj] = s_w[1024 + jg * 8 + jj];
                #pragma unroll
                for (int d = 0; d < 32; d++) {
                    float kd = kst[d];
                    #pragma unroll
                    for (int jj = 0; jj < 8; jj++) a8[jj] += kd * s_w[(jg * 8 + jj) * 32 + d];
                }
                #pragma unroll
                for (int jj = 0; jj < 8; jj++) {
                    float m = fminf(8.0f, fmaxf(-8.0f, a8[jj]));
                    R1[tk * 66 + jg * 8 + jj]      = __expf(m)  * mk;
                    R1[tk * 66 + 32 + jg * 8 + jj] = __expf(-m) * mk;
                }
            }
        }
        __syncthreads();
        // ---- stage vm chunk (coalesced, masked) -> R2 [128][34] ----
        {
            const float* Pv0 = g_P + (size_t)(t0 + c * 128) * 512 + 256 + h * 32;
            #pragma unroll
            for (int it = 0; it < 4; it++) {
                int idx = it * 256 + tid;
                int token = idx >> 3, c4 = idx & 7;
                float4 v = *(const float4*)(Pv0 + (size_t)token * 512 + c4 * 4);
                float m = s_mask[c * 128 + token];
                float* d = R2 + token * 34 + c4 * 4;
                d[0] = v.x * m; d[1] = v.y * m; d[2] = v.z * m; d[3] = v.w * m;
            }
        }
        __syncthreads();
        // ---- step B: 32 tokens per warp per chunk ----
        #pragma unroll 2
        for (int i = 0; i < 32; i++) {
            int nn = tg * 32 + i;
            // stride-66 rows: float4 would be misaligned for odd nn — use 2x float2
            float2 kfa = *(const float2*)&R1[nn * 66 + fbase];
            float2 kfb2 = *(const float2*)&R1[nn * 66 + fbase + 2];
            u64 kf2[4];
            kf2[0] = frep2(kfa.x); kf2[1] = frep2(kfa.y);
            kf2[2] = frep2(kfb2.x); kf2[3] = frep2(kfb2.y);
            const float* vmp = &R2[nn * 34 + dx * 8];
            u64 vm2[4];
            #pragma unroll
            for (int q = 0; q < 4; q++) vm2[q] = *(const u64*)(vmp + 2 * q);
            #pragma unroll
            for (int j = 0; j < 4; j++)
                #pragma unroll
                for (int q = 0; q < 4; q++) ffma2(acc2[j][q], kf2[j], vm2[q]);
            if (dx == 0) {
                ks[0] += kfa.x; ks[1] += kfa.y; ks[2] += kfb2.x; ks[3] += kfb2.y;
            }
        }
        __syncthreads();   // done reading R1/R2 for this chunk
    }

    // ---- spill partials into R1: kvp[2][4][1024] + ksp[256] ----
    float* kvp = R1;
    float* ksp = R1 + 8192;
    #pragma unroll
    for (int j = 0; j < 4; j++) {
        float2 u0 = funpk(acc2[j][0]), u1 = funpk(acc2[j][1]);
        float2 u2 = funpk(acc2[j][2]), u3 = funpk(acc2[j][3]);
        float* dst = &kvp[fhalf * 4096 + tg * 1024 + (fy * 4 + j) * 32 + dx * 8];
        *(float4*)dst       = make_float4(u0.x, u0.y, u1.x, u1.y);
        *(float4*)(dst + 4) = make_float4(u2.x, u2.y, u3.x, u3.y);
    }
    if (dx == 0) {
        #pragma unroll
        for (int j = 0; j < 4; j++) ksp[fhalf * 128 + tg * 32 + fy * 4 + j] = ks[j];
    }
    for (int i = tid; i < 1024; i += 256) s_w[i] = qfw[i];
    if (tid < 32) s_w[1024 + tid] = qfb[tid];
    __syncthreads();

    // ---- reduce 4 copies -> s_kv[2048] + s_ks[64] in R2 ----
    float* s_kv = R2;
    float* s_ks = R2 + 2048;
    {
        int e = tid * 8;
        int f = e >> 5, d0 = e & 31;
        const float* src = &kvp[(f >> 5) * 4096 + (f & 31) * 32 + d0];
        float4 r0 = make_float4(0, 0, 0, 0), r1 = make_float4(0, 0, 0, 0);
        #pragma unroll
        for (int c2 = 0; c2 < 4; c2++) {
            float4 p0 = *(const float4*)(src + c2 * 1024);
            float4 p1 = *(const float4*)(src + c2 * 1024 + 4);
            r0.x += p0.x; r0.y += p0.y; r0.z += p0.z; r0.w += p0.w;
            r1.x += p1.x; r1.y += p1.y; r1.z += p1.z; r1.w += p1.w;
        }
        *(float4*)&s_kv[e]     = r0;
        *(float4*)&s_kv[e + 4] = r1;
        if (tid < 64) {
            float s = 0.0f;
            #pragma unroll
            for (int c2 = 0; c2 < 4; c2++) s += ksp[(tid >> 5) * 128 + c2 * 32 + (tid & 31)];
            s_ks[tid] = s;
        }
    }
    __syncthreads();

    // ---- stage q (coalesced) -> R1 [256][33] ----
    {
        const float* Pq0 = g_P + (size_t)t0 * 512 + h * 32;
        #pragma unroll
        for (int it = 0; it < 8; it++) {
            int idx = it * 256 + tid;
            int token = idx >> 3, c4 = idx & 7;
            float4 v = *(const float4*)(Pq0 + (size_t)token * 512 + c4 * 4);
            float* d = R1 + token * 33 + c4 * 4;
            d[0] = v.x; d[1] = v.y; d[2] = v.z; d[3] = v.w;
        }
    }
    __syncthreads();

    // ---- step C: qf features (q re-read from smem), num/den ----
    u64 num2[16];
    #pragma unroll
    for (int q = 0; q < 16; q++) num2[q] = 0ull;
    float den = 0.0f;
    {
        const float* qrow = R1 + tid * 33;
        #pragma unroll
        for (int jg = 0; jg < 4; jg++) {
            float a8[8];
            #pragma unroll
            for (int jj = 0; jj < 8; jj++) a8[jj] = s_w[1024 + jg * 8 + jj];
            #pragma unroll
            for (int d = 0; d < 32; d++) {
                float qd = qrow[d];
                #pragma unroll
                for (int jj = 0; jj < 8; jj++) a8[jj] += qd * s_w[(jg * 8 + jj) * 32 + d];
            }
            #pragma unroll
            for (int jj = 0; jj < 8; jj++) {
                float m = fminf(8.0f, fmaxf(-8.0f, a8[jj]));
                float e  = __expf(m);
                float ei = __expf(-m);
                int f1 = jg * 8 + jj, f2 = f1 + 32;
                den += e  * s_ks[f1];
                den += ei * s_ks[f2];
                u64 e2 = frep2(e), ei2 = frep2(ei);
                const ulonglong2* k1 = (const ulonglong2*)&s_kv[f1 * 32];
                const ulonglong2* k2 = (const ulonglong2*)&s_kv[f2 * 32];
                #pragma unroll
                for (int q = 0; q < 8; q++) {
                    ulonglong2 ka = k1[q];
                    ffma2(num2[2 * q],     e2, ka.x);
                    ffma2(num2[2 * q + 1], e2, ka.y);
                }
                #pragma unroll
                for (int q = 0; q < 8; q++) {
                    ulonglong2 kb = k2[q];
                    ffma2(num2[2 * q],     ei2, kb.x);
                    ffma2(num2[2 * q + 1], ei2, kb.y);
                }
            }
        }
    }
    den = fmaxf(den, 1e-6f);
    float inv = 1.0f / den;
    __syncthreads();   // all threads done reading q (R1)

    // ---- stage g (coalesced) -> R1, gate in place, coop store ----
    {
        const float* Pg0 = g_P + (size_t)t0 * 512 + 384 + h * 32;
        #pragma unroll
        for (int it = 0; it < 8; it++) {
            int idx = it * 256 + tid;
            int token = idx >> 3, c4 = idx & 7;
            float4 v = *(const float4*)(Pg0 + (size_t)token * 512 + c4 * 4);
            float* d = R1 + token * 33 + c4 * 4;
            d[0] = v.x; d[1] = v.y; d[2] = v.z; d[3] = v.w;
        }
    }
    __syncthreads();
    {
        float* grow = R1 + tid * 33;
        #pragma unroll
        for (int i = 0; i < 8; i++) {
            float2 ua = funpk(num2[2 * i]);
            float2 ub = funpk(num2[2 * i + 1]);
            float g0 = grow[4 * i + 0], g1 = grow[4 * i + 1];
            float g2 = grow[4 * i + 2], g3 = grow[4 * i + 3];
            grow[4 * i + 0] = __fdividef(1.0f, 1.0f + __expf(-g0)) * ua.x * inv;
            grow[4 * i + 1] = __fdividef(1.0f, 1.0f + __expf(-g1)) * ua.y * inv;
            grow[4 * i + 2] = __fdividef(1.0f, 1.0f + __expf(-g2)) * ub.x * inv;
            grow[4 * i + 3] = __fdividef(1.0f, 1.0f + __expf(-g3)) * ub.y * inv;
        }
    }
    __syncthreads();
    {
        float* GA0 = g_GA + (size_t)t0 * 128 + h * 32;
        #pragma unroll
        for (int it = 0; it < 8; it++) {
            int idx = it * 256 + tid;
            int token = idx >> 3, c4 = idx & 7;
            const float* s = R1 + token * 33 + c4 * 4;
            float4 o = make_float4(s[0], s[1], s[2], s[3]);
            *(float4*)(GA0 + (size_t)token * 128 + c4 * 4) = o;
        }
    }
}

// ---------------- launcher ----------------
extern "C" void kernel_launch(void* const* d_in, const int* in_sizes, int n_in,
                              void* d_out, int out_size) {
    const float* z    = (const float*)d_in[0];
    const int*   pm   = (const int*)  d_in[1];
    const float* lnw  = (const float*)d_in[2];
    const float* lnb  = (const float*)d_in[3];
    const float* qw   = (const float*)d_in[4];
    const float* qb   = (const float*)d_in[5];
    const float* kw   = (const float*)d_in[6];
    const float* kb   = (const float*)d_in[7];
    const float* vw   = (const float*)d_in[8];
    const float* vb   = (const float*)d_in[9];
    const float* qfw  = (const float*)d_in[10];
    const float* qfb  = (const float*)d_in[11];
    const float* kfw  = (const float*)d_in[12];
    const float* kfb  = (const float*)d_in[13];
    const float* gw   = (const float*)d_in[14];
    const float* gb   = (const float*)d_in[15];
    const float* ow   = (const float*)d_in[16];
    const float* ob   = (const float*)d_in[17];
    float* out = (float*)d_out;

    static int attr_set = 0;
    if (!attr_set) {
        cudaFuncSetAttribute(attn_kernel, cudaFuncAttributeMaxDynamicSharedMemorySize, 56448);
        cudaFuncSetAttribute(mma_gemm<1>, cudaFuncAttributeMaxDynamicSharedMemorySize, 104448);
        cudaFuncSetAttribute(mma_gemm<2>, cudaFuncAttributeMaxDynamicSharedMemorySize, 104448);
        attr_set = 1;
    }

    pack_kernel<<<320, 256>>>(qw, kw, vw, gw, qb, kb, vb, gb, ow);
    ln_kernel<<<8192, 256>>>(z, lnw, lnb);
    mma_gemm<1><<<dim3(1024, 4), 256, 104448>>>(nullptr, nullptr, nullptr);
    attn_kernel<<<dim3(256, 4), 256, 56448>>>(pm, qfw, qfb, kfw, kfb);
    mma_gemm<2><<<dim3(1024, 1), 256, 104448>>>(ob, pm, out);
}